// round 1
// baseline (speedup 1.0000x reference)
#include <cuda_runtime.h>
#include <math.h>

// Problem constants (fixed by setup_inputs)
#define S_LEN   2048
#define DMODEL  1024
#define NHEADS  16
#define DK      64
#define BATCH   2
#define MROWS   (BATCH * S_LEN)   // 4096

// Scratch (device globals: allocation-free per harness rules)
__device__ float g_Q[(size_t)MROWS * DMODEL];
__device__ float g_K[(size_t)MROWS * DMODEL];
__device__ float g_V[(size_t)MROWS * DMODEL];
__device__ float g_O[(size_t)MROWS * DMODEL];

// ---------------------------------------------------------------------------
// SGEMM: C[M=4096, N=1024] = A[M, K=1024] @ W[K, N] + bias[N]
// 128x128 block tile, BK=8, 256 threads, 8x8 micro-tile per thread.
// ---------------------------------------------------------------------------
__device__ __forceinline__ void sgemm_body(const float* __restrict__ A,
                                           const float* __restrict__ W,
                                           const float* __restrict__ bias,
                                           float* __restrict__ C) {
    const int K = DMODEL;
    const int N = DMODEL;

    __shared__ float As[8][128];   // [k][m]
    __shared__ float Bs[8][128];   // [k][n]

    const int tid = threadIdx.x;
    const int tm  = tid >> 4;          // 0..15
    const int tn  = tid & 15;          // 0..15
    const int m0  = blockIdx.y * 128;
    const int n0  = blockIdx.x * 128;

    // A-tile load mapping: 128 rows x 8 cols; thread -> (row = tid/2, 4 cols)
    const int ar = tid >> 1;
    const int ak = (tid & 1) << 2;
    // B-tile load mapping: 8 rows x 128 cols; thread -> (row = tid/32, 4 cols)
    const int br = tid >> 5;
    const int bc = (tid & 31) << 2;

    const float* Ap = A + (size_t)(m0 + ar) * K + ak;
    const float* Wp = W + (size_t)br * N + n0 + bc;

    float acc[8][8];
#pragma unroll
    for (int i = 0; i < 8; i++)
#pragma unroll
        for (int j = 0; j < 8; j++) acc[i][j] = 0.0f;

    for (int k0 = 0; k0 < K; k0 += 8) {
        float4 av = *(const float4*)(Ap + k0);
        float4 bv = *(const float4*)(Wp + (size_t)k0 * N);
        As[ak + 0][ar] = av.x;
        As[ak + 1][ar] = av.y;
        As[ak + 2][ar] = av.z;
        As[ak + 3][ar] = av.w;
        *(float4*)&Bs[br][bc] = bv;
        __syncthreads();

#pragma unroll
        for (int kk = 0; kk < 8; kk++) {
            float a[8], b[8];
            *(float4*)(a)     = *(const float4*)&As[kk][tm * 8];
            *(float4*)(a + 4) = *(const float4*)&As[kk][tm * 8 + 4];
            *(float4*)(b)     = *(const float4*)&Bs[kk][tn * 8];
            *(float4*)(b + 4) = *(const float4*)&Bs[kk][tn * 8 + 4];
#pragma unroll
            for (int i = 0; i < 8; i++)
#pragma unroll
                for (int j = 0; j < 8; j++) acc[i][j] += a[i] * b[j];
        }
        __syncthreads();
    }

    float bs[8];
#pragma unroll
    for (int j = 0; j < 8; j++) bs[j] = bias[n0 + tn * 8 + j];

#pragma unroll
    for (int i = 0; i < 8; i++) {
        const int row = m0 + tm * 8 + i;
        float4 o1, o2;
        o1.x = acc[i][0] + bs[0]; o1.y = acc[i][1] + bs[1];
        o1.z = acc[i][2] + bs[2]; o1.w = acc[i][3] + bs[3];
        o2.x = acc[i][4] + bs[4]; o2.y = acc[i][5] + bs[5];
        o2.z = acc[i][6] + bs[6]; o2.w = acc[i][7] + bs[7];
        *(float4*)&C[(size_t)row * N + n0 + tn * 8]     = o1;
        *(float4*)&C[(size_t)row * N + n0 + tn * 8 + 4] = o2;
    }
}

__global__ void __launch_bounds__(256) sgemm_qkv(
    const float* __restrict__ Xq, const float* __restrict__ Xk, const float* __restrict__ Xv,
    const float* __restrict__ Wq, const float* __restrict__ Wk, const float* __restrict__ Wv,
    const float* __restrict__ Bq, const float* __restrict__ Bk, const float* __restrict__ Bv) {
    if (blockIdx.z == 0)      sgemm_body(Xq, Wq, Bq, g_Q);
    else if (blockIdx.z == 1) sgemm_body(Xk, Wk, Bk, g_K);
    else                      sgemm_body(Xv, Wv, Bv, g_V);
}

__global__ void __launch_bounds__(256) sgemm_out(
    const float* __restrict__ Wo, const float* __restrict__ Bo, float* __restrict__ C) {
    sgemm_body(g_O, Wo, Bo, C);
}

// ---------------------------------------------------------------------------
// Flash attention (fp32): block = (q-tile of 64 rows, head h, batch b).
// 128 threads; thread micro-tile = 4 q-rows x 8 k-cols (and 4 q x 8 d for O).
// Online softmax with causal tile skipping. Lookahead mask is read from
// memory on the diagonal tile; padding mask is applied on every tile.
// ---------------------------------------------------------------------------
#define FL_SMEM (4 * 64 * 65 * 4)   // Qs, Ks, Vs, Ps : [64][65] floats each

__global__ void __launch_bounds__(128) flash_attn(const float* __restrict__ pad_mask,
                                                  const float* __restrict__ look_mask) {
    extern __shared__ float sm[];
    float* Qs = sm;              // [d][m]  (d-major, padded 65)
    float* Ks = sm + 64 * 65;    // [d][n]
    float* Vs = sm + 2 * 64 * 65;// [k][d]
    float* Ps = sm + 3 * 64 * 65;// [k][m]

    const int tid  = threadIdx.x;
    const int tcol = tid & 7;    // 8 column-threads (x8 cols each)
    const int trow = tid >> 3;   // 16 row-threads (x4 rows each)
    const int qt = blockIdx.x;
    const int h  = blockIdx.y;
    const int b  = blockIdx.z;
    const int q0 = qt * 64;

    // Load Q tile (64 x 64) transposed into Qs[d][m]
    const float* Qg = g_Q + (size_t)(b * S_LEN + q0) * DMODEL + h * DK;
#pragma unroll
    for (int i = 0; i < 8; i++) {
        int f   = tid + i * 128;       // 0..1023 float4 slots
        int row = f >> 4;              // 0..63
        int c4  = (f & 15) << 2;       // 0..60
        float4 v = *(const float4*)(Qg + (size_t)row * DMODEL + c4);
        Qs[(c4 + 0) * 65 + row] = v.x;
        Qs[(c4 + 1) * 65 + row] = v.y;
        Qs[(c4 + 2) * 65 + row] = v.z;
        Qs[(c4 + 3) * 65 + row] = v.w;
    }

    float o[4][8];
    float mrow[4], lrow[4];
#pragma unroll
    for (int i = 0; i < 4; i++) {
        mrow[i] = -INFINITY;
        lrow[i] = 0.0f;
#pragma unroll
        for (int j = 0; j < 8; j++) o[i][j] = 0.0f;
    }

    const int nkt = qt + 1;    // causal: only tiles with k0 <= q0
    for (int kt = 0; kt < nkt; kt++) {
        __syncthreads();   // previous iter's PV reads done before K/V/Ps reuse
        const int k0 = kt * 64;
        const float* Kg = g_K + (size_t)(b * S_LEN + k0) * DMODEL + h * DK;
        const float* Vg = g_V + (size_t)(b * S_LEN + k0) * DMODEL + h * DK;
#pragma unroll
        for (int i = 0; i < 8; i++) {
            int f   = tid + i * 128;
            int row = f >> 4;
            int c4  = (f & 15) << 2;
            float4 kv = *(const float4*)(Kg + (size_t)row * DMODEL + c4);
            Ks[(c4 + 0) * 65 + row] = kv.x;
            Ks[(c4 + 1) * 65 + row] = kv.y;
            Ks[(c4 + 2) * 65 + row] = kv.z;
            Ks[(c4 + 3) * 65 + row] = kv.w;
            float4 vv = *(const float4*)(Vg + (size_t)row * DMODEL + c4);
            Vs[row * 65 + c4 + 0] = vv.x;
            Vs[row * 65 + c4 + 1] = vv.y;
            Vs[row * 65 + c4 + 2] = vv.z;
            Vs[row * 65 + c4 + 3] = vv.w;
        }
        __syncthreads();

        // S = Q @ K^T  (64x64x64)
        float s[4][8];
#pragma unroll
        for (int i = 0; i < 4; i++)
#pragma unroll
            for (int j = 0; j < 8; j++) s[i][j] = 0.0f;

#pragma unroll 8
        for (int d = 0; d < 64; d++) {
            float a[4], bb[8];
#pragma unroll
            for (int i = 0; i < 4; i++) a[i] = Qs[d * 65 + trow * 4 + i];
#pragma unroll
            for (int j = 0; j < 8; j++) bb[j] = Ks[d * 65 + tcol * 8 + j];
#pragma unroll
            for (int i = 0; i < 4; i++)
#pragma unroll
                for (int j = 0; j < 8; j++) s[i][j] += a[i] * bb[j];
        }

        // scale + masks
        float pj[8];
#pragma unroll
        for (int j = 0; j < 8; j++)
            pj[j] = pad_mask[b * S_LEN + k0 + tcol * 8 + j];

        const bool diag = (kt == qt);
#pragma unroll
        for (int i = 0; i < 4; i++) {
            float lk[8];
            if (diag) {
                const float* lrp = look_mask + (size_t)(q0 + trow * 4 + i) * S_LEN + k0 + tcol * 8;
                float4 l1 = *(const float4*)(lrp);
                float4 l2 = *(const float4*)(lrp + 4);
                lk[0] = l1.x; lk[1] = l1.y; lk[2] = l1.z; lk[3] = l1.w;
                lk[4] = l2.x; lk[5] = l2.y; lk[6] = l2.z; lk[7] = l2.w;
            } else {
#pragma unroll
                for (int j = 0; j < 8; j++) lk[j] = 0.0f;
            }
#pragma unroll
            for (int j = 0; j < 8; j++)
                s[i][j] = s[i][j] * 0.125f + pj[j] + lk[j];

            // row max across this thread's 8 cols, then across the 8 lanes of the row-group
            float tmax = s[i][0];
#pragma unroll
            for (int j = 1; j < 8; j++) tmax = fmaxf(tmax, s[i][j]);
            tmax = fmaxf(tmax, __shfl_xor_sync(0xffffffffu, tmax, 1));
            tmax = fmaxf(tmax, __shfl_xor_sync(0xffffffffu, tmax, 2));
            tmax = fmaxf(tmax, __shfl_xor_sync(0xffffffffu, tmax, 4));

            const float mnew = fmaxf(mrow[i], tmax);
            const float corr = __expf(mrow[i] - mnew);   // exp(-inf) = 0 on first tile
            float rsum = 0.0f;
#pragma unroll
            for (int j = 0; j < 8; j++) {
                float p = __expf(s[i][j] - mnew);
                s[i][j] = p;
                rsum += p;
            }
            rsum += __shfl_xor_sync(0xffffffffu, rsum, 1);
            rsum += __shfl_xor_sync(0xffffffffu, rsum, 2);
            rsum += __shfl_xor_sync(0xffffffffu, rsum, 4);

            lrow[i] = lrow[i] * corr + rsum;
            mrow[i] = mnew;
#pragma unroll
            for (int j = 0; j < 8; j++) o[i][j] *= corr;
        }

        // store P transposed into Ps[k][m]
#pragma unroll
        for (int i = 0; i < 4; i++)
#pragma unroll
            for (int j = 0; j < 8; j++)
                Ps[(tcol * 8 + j) * 65 + trow * 4 + i] = s[i][j];
        __syncthreads();

        // O += P @ V  (64x64x64)
#pragma unroll 8
        for (int k = 0; k < 64; k++) {
            float a[4], bb[8];
#pragma unroll
            for (int i = 0; i < 4; i++) a[i] = Ps[k * 65 + trow * 4 + i];
#pragma unroll
            for (int j = 0; j < 8; j++) bb[j] = Vs[k * 65 + tcol * 8 + j];
#pragma unroll
            for (int i = 0; i < 4; i++)
#pragma unroll
                for (int j = 0; j < 8; j++) o[i][j] += a[i] * bb[j];
        }
    }

    // epilogue: normalize + write to g_O (concat layout: [b*S + q][h*64 + d])
#pragma unroll
    for (int i = 0; i < 4; i++) {
        const int row = q0 + trow * 4 + i;
        const float inv = 1.0f / lrow[i];
        float4 w1, w2;
        w1.x = o[i][0] * inv; w1.y = o[i][1] * inv; w1.z = o[i][2] * inv; w1.w = o[i][3] * inv;
        w2.x = o[i][4] * inv; w2.y = o[i][5] * inv; w2.z = o[i][6] * inv; w2.w = o[i][7] * inv;
        float* Og = g_O + (size_t)(b * S_LEN + row) * DMODEL + h * DK + tcol * 8;
        *(float4*)(Og)     = w1;
        *(float4*)(Og + 4) = w2;
    }
}

// ---------------------------------------------------------------------------
// Launch
// ---------------------------------------------------------------------------
extern "C" void kernel_launch(void* const* d_in, const int* in_sizes, int n_in,
                              void* d_out, int out_size) {
    const float* query = (const float*)d_in[0];
    const float* key   = (const float*)d_in[1];
    const float* value = (const float*)d_in[2];
    const float* pad   = (const float*)d_in[3];
    const float* look  = (const float*)d_in[4];
    const float* wq    = (const float*)d_in[5];
    const float* wk    = (const float*)d_in[6];
    const float* wv    = (const float*)d_in[7];
    const float* wo    = (const float*)d_in[8];
    const float* bq    = (const float*)d_in[9];
    const float* bk    = (const float*)d_in[10];
    const float* bv    = (const float*)d_in[11];
    const float* bo    = (const float*)d_in[12];
    float* out = (float*)d_out;

    // Opt-in to >48KB dynamic smem for the flash kernel (idempotent, capture-safe).
    cudaFuncSetAttribute(flash_attn, cudaFuncAttributeMaxDynamicSharedMemorySize, FL_SMEM);

    // 1) Q/K/V projections: 3 x (4096x1024x1024) GEMM
    dim3 gq(DMODEL / 128, MROWS / 128, 3);
    sgemm_qkv<<<gq, 256>>>(query, key, value, wq, wk, wv, bq, bk, bv);

    // 2) causal flash attention per (q-tile, head, batch)
    dim3 ga(S_LEN / 64, NHEADS, BATCH);
    flash_attn<<<ga, 128, FL_SMEM>>>(pad, look);

    // 3) output projection -> d_out
    dim3 go(DMODEL / 128, MROWS / 128, 1);
    sgemm_out<<<go, 256>>>(wo, bo, out);
}

// round 3
// speedup vs baseline: 2.8130x; 2.8130x over previous
#include <cuda_runtime.h>
#include <cuda_bf16.h>
#include <math.h>
#include <stdint.h>

// Problem constants (fixed by setup_inputs)
#define S_LEN   2048
#define DMODEL  1024
#define NHEADS  16
#define DK      64
#define BATCH   2
#define MROWS   (BATCH * S_LEN)   // 4096

typedef unsigned short ushort_t;

// ---------------------------------------------------------------------------
// Device scratch (allocation-free per harness rules)
// ---------------------------------------------------------------------------
__device__ __align__(16) float g_Q[(size_t)MROWS * DMODEL];
__device__ __align__(16) float g_K[(size_t)MROWS * DMODEL];
__device__ __align__(16) float g_V[(size_t)MROWS * DMODEL];
__device__ __align__(16) float g_O[(size_t)MROWS * DMODEL];

// bf16 hi/lo splits of activations (K-major [4096][1024])
__device__ __align__(16) ushort_t g_Xhi[(size_t)MROWS * DMODEL];
__device__ __align__(16) ushort_t g_Xlo[(size_t)MROWS * DMODEL];
__device__ __align__(16) ushort_t g_Yhi[(size_t)MROWS * DMODEL];
__device__ __align__(16) ushort_t g_Ylo[(size_t)MROWS * DMODEL];
__device__ __align__(16) ushort_t g_Zhi[(size_t)MROWS * DMODEL];
__device__ __align__(16) ushort_t g_Zlo[(size_t)MROWS * DMODEL];
__device__ __align__(16) ushort_t g_Ohi[(size_t)MROWS * DMODEL];
__device__ __align__(16) ushort_t g_Olo[(size_t)MROWS * DMODEL];

// bf16 hi/lo splits of TRANSPOSED weights: Wt[n][k] = W[k][n]
__device__ __align__(16) ushort_t g_WqThi[(size_t)DMODEL * DMODEL];
__device__ __align__(16) ushort_t g_WqTlo[(size_t)DMODEL * DMODEL];
__device__ __align__(16) ushort_t g_WkThi[(size_t)DMODEL * DMODEL];
__device__ __align__(16) ushort_t g_WkTlo[(size_t)DMODEL * DMODEL];
__device__ __align__(16) ushort_t g_WvThi[(size_t)DMODEL * DMODEL];
__device__ __align__(16) ushort_t g_WvTlo[(size_t)DMODEL * DMODEL];
__device__ __align__(16) ushort_t g_WoThi[(size_t)DMODEL * DMODEL];
__device__ __align__(16) ushort_t g_WoTlo[(size_t)DMODEL * DMODEL];

// ---------------------------------------------------------------------------
// Low-level helpers (sm_80-class: mma.sync / ldmatrix / cp.async)
// ---------------------------------------------------------------------------
__device__ __forceinline__ uint32_t smem_u32(const void* p) {
    uint32_t a;
    asm("{ .reg .u64 t; cvta.to.shared.u64 t, %1; cvt.u32.u64 %0, t; }" : "=r"(a) : "l"(p));
    return a;
}

// D = A(bf16 m16k16) * B(bf16 k16n8) + D (f32)
__device__ __forceinline__ void mma_bf16(float* c, const uint32_t* a, const uint32_t* b) {
    asm volatile(
        "mma.sync.aligned.m16n8k16.row.col.f32.bf16.bf16.f32 "
        "{%0,%1,%2,%3}, {%4,%5,%6,%7}, {%8,%9}, {%0,%1,%2,%3};"
        : "+f"(c[0]), "+f"(c[1]), "+f"(c[2]), "+f"(c[3])
        : "r"(a[0]), "r"(a[1]), "r"(a[2]), "r"(a[3]), "r"(b[0]), "r"(b[1]));
}
__device__ __forceinline__ void ldsm_x4(uint32_t* r, uint32_t addr) {
    asm volatile("ldmatrix.sync.aligned.m8n8.x4.shared.b16 {%0,%1,%2,%3}, [%4];"
        : "=r"(r[0]), "=r"(r[1]), "=r"(r[2]), "=r"(r[3]) : "r"(addr));
}
__device__ __forceinline__ void ldsm_x4_t(uint32_t* r, uint32_t addr) {
    asm volatile("ldmatrix.sync.aligned.m8n8.x4.trans.shared.b16 {%0,%1,%2,%3}, [%4];"
        : "=r"(r[0]), "=r"(r[1]), "=r"(r[2]), "=r"(r[3]) : "r"(addr));
}
__device__ __forceinline__ void cp16(uint32_t dst, const void* src) {
    asm volatile("cp.async.cg.shared.global [%0], [%1], 16;" :: "r"(dst), "l"(src));
}
__device__ __forceinline__ void cp_commit() {
    asm volatile("cp.async.commit_group;" ::: "memory");
}
template <int N> __device__ __forceinline__ void cp_wait() {
    asm volatile("cp.async.wait_group %0;" :: "n"(N) : "memory");
}

// Split fp32 -> bf16 hi + lo
__device__ __forceinline__ void split1(float x, ushort_t& h, ushort_t& l) {
    __nv_bfloat16 hb = __float2bfloat16(x);
    float rem = x - __bfloat162float(hb);
    __nv_bfloat16 lb = __float2bfloat16(rem);
    h = __bfloat16_as_ushort(hb);
    l = __bfloat16_as_ushort(lb);
}

// Split a float4 into hi/lo bf16 pairs and store (4 consecutive elems) to smem
__device__ __forceinline__ void st_split4(char* H, char* L, int elem_off, float4 v) {
    __nv_bfloat162 h0, h1, l0, l1;
    h0.x = __float2bfloat16(v.x); l0.x = __float2bfloat16(v.x - __bfloat162float(h0.x));
    h0.y = __float2bfloat16(v.y); l0.y = __float2bfloat16(v.y - __bfloat162float(h0.y));
    h1.x = __float2bfloat16(v.z); l1.x = __float2bfloat16(v.z - __bfloat162float(h1.x));
    h1.y = __float2bfloat16(v.w); l1.y = __float2bfloat16(v.w - __bfloat162float(h1.y));
    *(__nv_bfloat162*)(H + (size_t)elem_off * 2)     = h0;
    *(__nv_bfloat162*)(H + (size_t)elem_off * 2 + 4) = h1;
    *(__nv_bfloat162*)(L + (size_t)elem_off * 2)     = l0;
    *(__nv_bfloat162*)(L + (size_t)elem_off * 2 + 4) = l1;
}

// ---------------------------------------------------------------------------
// Prep kernels: split activations; transpose+split weights
// ---------------------------------------------------------------------------
__global__ void __launch_bounds__(256) split_kernel(const float* __restrict__ x,
                                                    ushort_t* __restrict__ hi,
                                                    ushort_t* __restrict__ lo,
                                                    int n4) {
    int i = blockIdx.x * 256 + threadIdx.x;
    if (i >= n4) return;
    float4 v = ((const float4*)x)[i];
    ushort4 h, l;
    split1(v.x, h.x, l.x);
    split1(v.y, h.y, l.y);
    split1(v.z, h.z, l.z);
    split1(v.w, h.w, l.w);
    ((ushort4*)hi)[i] = h;
    ((ushort4*)lo)[i] = l;
}

__global__ void __launch_bounds__(256) wsplit_kernel(const float* __restrict__ w0,
                                                     const float* __restrict__ w1,
                                                     const float* __restrict__ w2,
                                                     const float* __restrict__ w3) {
    __shared__ float t[32][33];
    const float* W;
    ushort_t *TH, *TL;
    switch (blockIdx.z) {
        case 0: W = w0; TH = g_WqThi; TL = g_WqTlo; break;
        case 1: W = w1; TH = g_WkThi; TL = g_WkTlo; break;
        case 2: W = w2; TH = g_WvThi; TL = g_WvTlo; break;
        default: W = w3; TH = g_WoThi; TL = g_WoTlo; break;
    }
    int tx = threadIdx.x & 31, ty = threadIdx.x >> 5;   // 32 x 8
    int n0 = blockIdx.x * 32, k0 = blockIdx.y * 32;
#pragma unroll
    for (int j = 0; j < 4; j++)
        t[ty + 8 * j][tx] = W[(size_t)(k0 + ty + 8 * j) * DMODEL + n0 + tx];
    __syncthreads();
#pragma unroll
    for (int j = 0; j < 4; j++) {
        float v = t[tx][ty + 8 * j];
        ushort_t h, l;
        split1(v, h, l);
        size_t o = (size_t)(n0 + ty + 8 * j) * DMODEL + k0 + tx;
        TH[o] = h;
        TL[o] = l;
    }
}

// ---------------------------------------------------------------------------
// HMMA GEMM (bf16x3): C[4096,1024] = A @ Wt^T + bias
// 128x128 tile, BK=32, 256 threads (8 warps as 4m x 2n, warp tile 32x64),
// cp.async double buffer. smem row stride 40 elems (80B, ldmatrix conflict-free).
// ---------------------------------------------------------------------------
#define GT_STRIDE 40
#define GT_MAT    (128 * GT_STRIDE * 2)     // 10240 B per matrix tile
#define GT_BUF    (4 * GT_MAT)              // Ahi, Alo, Bhi, Blo
#define GEMM_SMEM (2 * GT_BUF)              // 81920 B

__device__ __forceinline__ void gemm_mma_body(const ushort_t* __restrict__ ahi,
                                              const ushort_t* __restrict__ alo,
                                              const ushort_t* __restrict__ bhi,
                                              const ushort_t* __restrict__ blo,
                                              const float* __restrict__ bias,
                                              float* __restrict__ C) {
    extern __shared__ char smem[];
    const uint32_t sb = smem_u32(smem);
    const int tid = threadIdx.x;
    const int lane = tid & 31;
    const int wid = tid >> 5;
    const int wm = wid >> 1;          // 0..3
    const int wn = wid & 1;           // 0..1
    const int m0 = blockIdx.y * 128;
    const int n0 = blockIdx.x * 128;

    const ushort_t* srcs[4] = { ahi + (size_t)m0 * DMODEL, alo + (size_t)m0 * DMODEL,
                                bhi + (size_t)n0 * DMODEL, blo + (size_t)n0 * DMODEL };

    auto load_chunk = [&](int c, int buf) {
        uint32_t dbase = sb + buf * GT_BUF;
#pragma unroll
        for (int mt = 0; mt < 4; mt++) {
#pragma unroll
            for (int i = 0; i < 2; i++) {
                int idx = tid + i * 256;
                int row = idx >> 2, seg = idx & 3;
                const ushort_t* src = srcs[mt] + (size_t)row * DMODEL + c * 32 + seg * 8;
                cp16(dbase + mt * GT_MAT + (row * GT_STRIDE + seg * 8) * 2, src);
            }
        }
    };

    float acc[2][8][4];
#pragma unroll
    for (int mi = 0; mi < 2; mi++)
#pragma unroll
        for (int j = 0; j < 8; j++)
#pragma unroll
            for (int q = 0; q < 4; q++) acc[mi][j][q] = 0.0f;

    load_chunk(0, 0);
    cp_commit();

    for (int c = 0; c < 32; c++) {
        if (c + 1 < 32) { load_chunk(c + 1, (c + 1) & 1); cp_commit(); }
        if (c + 1 < 32) cp_wait<1>(); else cp_wait<0>();
        __syncthreads();

        const uint32_t base = sb + (c & 1) * GT_BUF;
        const uint32_t A_h = base, A_l = base + GT_MAT;
        const uint32_t B_h = base + 2 * GT_MAT, B_l = base + 3 * GT_MAT;
#pragma unroll
        for (int ks = 0; ks < 2; ks++) {
            uint32_t ah[2][4], al[2][4];
#pragma unroll
            for (int mi = 0; mi < 2; mi++) {
                int row = wm * 32 + mi * 16 + (lane & 15);
                int col = ks * 16 + (lane >> 4) * 8;
                uint32_t off = (row * GT_STRIDE + col) * 2;
                ldsm_x4(ah[mi], A_h + off);
                ldsm_x4(al[mi], A_l + off);
            }
            uint32_t bh[8][2], bl[8][2];
#pragma unroll
            for (int j2 = 0; j2 < 4; j2++) {
                int nr = wn * 64 + j2 * 16 + (lane & 7) + ((lane & 16) ? 8 : 0);
                int kc = ks * 16 + ((lane & 8) ? 8 : 0);
                uint32_t off = (nr * GT_STRIDE + kc) * 2;
                uint32_t t[4];
                ldsm_x4(t, B_h + off);
                bh[2 * j2][0] = t[0]; bh[2 * j2][1] = t[1];
                bh[2 * j2 + 1][0] = t[2]; bh[2 * j2 + 1][1] = t[3];
                ldsm_x4(t, B_l + off);
                bl[2 * j2][0] = t[0]; bl[2 * j2][1] = t[1];
                bl[2 * j2 + 1][0] = t[2]; bl[2 * j2 + 1][1] = t[3];
            }
#pragma unroll
            for (int mi = 0; mi < 2; mi++)
#pragma unroll
                for (int j = 0; j < 8; j++) {
                    mma_bf16(acc[mi][j], ah[mi], bh[j]);
                    mma_bf16(acc[mi][j], ah[mi], bl[j]);
                    mma_bf16(acc[mi][j], al[mi], bh[j]);
                }
        }
        __syncthreads();
    }

    // epilogue: fragments -> gmem with bias (float2 per pair)
#pragma unroll
    for (int mi = 0; mi < 2; mi++) {
#pragma unroll
        for (int j = 0; j < 8; j++) {
            int row = m0 + wm * 32 + mi * 16 + (lane >> 2);
            int col = n0 + wn * 64 + j * 8 + (lane & 3) * 2;
            float2 bb = *(const float2*)&bias[col];
            float2 w0 = { acc[mi][j][0] + bb.x, acc[mi][j][1] + bb.y };
            float2 w1 = { acc[mi][j][2] + bb.x, acc[mi][j][3] + bb.y };
            *(float2*)&C[(size_t)row * DMODEL + col] = w0;
            *(float2*)&C[(size_t)(row + 8) * DMODEL + col] = w1;
        }
    }
}

__global__ void __launch_bounds__(256) gemm_qkv_tc(const float* __restrict__ bq,
                                                   const float* __restrict__ bk,
                                                   const float* __restrict__ bv) {
    if (blockIdx.z == 0)      gemm_mma_body(g_Xhi, g_Xlo, g_WqThi, g_WqTlo, bq, g_Q);
    else if (blockIdx.z == 1) gemm_mma_body(g_Yhi, g_Ylo, g_WkThi, g_WkTlo, bk, g_K);
    else                      gemm_mma_body(g_Zhi, g_Zlo, g_WvThi, g_WvTlo, bv, g_V);
}

__global__ void __launch_bounds__(256) gemm_out_tc(const float* __restrict__ bo,
                                                   float* __restrict__ C) {
    gemm_mma_body(g_Ohi, g_Olo, g_WoThi, g_WoTlo, bo, C);
}

// ---------------------------------------------------------------------------
// HMMA flash attention: block = (64 q-rows, head, batch), 128 threads / 4 warps.
// Warp owns 16 q-rows. S and PV via mma.sync bf16x3; softmax on C-fragments.
// smem tiles stride 72 elems (144B): ldmatrix conflict-free.
// ---------------------------------------------------------------------------
#define FL_STRIDE 72
#define FL_TILE   (64 * FL_STRIDE * 2)      // 9216 B
#define FL_QH 0
#define FL_QL (FL_QH + FL_TILE)
#define FL_KH (FL_QL + FL_TILE)
#define FL_KL (FL_KH + FL_TILE)
#define FL_VH (FL_KL + FL_TILE)
#define FL_VL (FL_VH + FL_TILE)
#define FL_PH (FL_VL + FL_TILE)
#define FL_PL (FL_PH + FL_TILE)
#define FL_MS (FL_PL + FL_TILE)             // 64 x 68 fp32 = 17408 B
#define FL_PAD (FL_MS + 64 * 68 * 4)        // 64 fp32
#define FL_SMEM (FL_PAD + 256)

__global__ void __launch_bounds__(128) flash_mma(const float* __restrict__ pad_mask,
                                                 const float* __restrict__ look_mask) {
    extern __shared__ char smc[];
    char* QH = smc + FL_QH; char* QL = smc + FL_QL;
    char* KH = smc + FL_KH; char* KL = smc + FL_KL;
    char* VH = smc + FL_VH; char* VL = smc + FL_VL;
    char* PH = smc + FL_PH; char* PL = smc + FL_PL;
    float* Ms   = (float*)(smc + FL_MS);
    float* pads = (float*)(smc + FL_PAD);

    const uint32_t uQH = smem_u32(QH), uQL = smem_u32(QL);
    const uint32_t uKH = smem_u32(KH), uKL = smem_u32(KL);
    const uint32_t uVH = smem_u32(VH), uVL = smem_u32(VL);
    const uint32_t uPH = smem_u32(PH), uPL = smem_u32(PL);

    const int tid = threadIdx.x;
    const int lane = tid & 31;
    const int warp = tid >> 5;
    const int qt = blockIdx.x, h = blockIdx.y, b = blockIdx.z;
    const int q0 = qt * 64;

    // Load + split Q tile (64x64 fp32 -> bf16 hi/lo)
    const float* Qg = g_Q + (size_t)(b * S_LEN + q0) * DMODEL + h * DK;
#pragma unroll
    for (int i = 0; i < 8; i++) {
        int idx = tid + i * 128;
        int row = idx >> 4, c4 = (idx & 15) * 4;
        st_split4(QH, QL, row * FL_STRIDE + c4, *(const float4*)(Qg + (size_t)row * DMODEL + c4));
    }

    float o[8][4];
    float mrow[2] = { -INFINITY, -INFINITY };
    float lrow[2] = { 0.0f, 0.0f };
#pragma unroll
    for (int j = 0; j < 8; j++)
#pragma unroll
        for (int q = 0; q < 4; q++) o[j][q] = 0.0f;

    for (int kt = 0; kt <= qt; kt++) {
        __syncthreads();   // prior PV reads of K/V/P done before overwrite (also covers Q init)
        const int k0 = kt * 64;
        const float* Kg = g_K + (size_t)(b * S_LEN + k0) * DMODEL + h * DK;
        const float* Vg = g_V + (size_t)(b * S_LEN + k0) * DMODEL + h * DK;
        const bool diag = (kt == qt);
#pragma unroll
        for (int i = 0; i < 8; i++) {
            int idx = tid + i * 128;
            int row = idx >> 4, c4 = (idx & 15) * 4;
            st_split4(KH, KL, row * FL_STRIDE + c4, *(const float4*)(Kg + (size_t)row * DMODEL + c4));
            st_split4(VH, VL, row * FL_STRIDE + c4, *(const float4*)(Vg + (size_t)row * DMODEL + c4));
        }
        if (diag) {
#pragma unroll
            for (int i = 0; i < 8; i++) {
                int idx = tid + i * 128;
                int row = idx >> 4, c4 = (idx & 15) * 4;
                *(float4*)&Ms[row * 68 + c4] =
                    *(const float4*)(look_mask + (size_t)(q0 + row) * S_LEN + k0 + c4);
            }
        }
        if (tid < 64) pads[tid] = pad_mask[b * S_LEN + k0 + tid];
        __syncthreads();

        // ---- S = Q @ K^T (64x64x64, bf16x3) ----
        float sc[8][4];
#pragma unroll
        for (int j = 0; j < 8; j++)
#pragma unroll
            for (int q = 0; q < 4; q++) sc[j][q] = 0.0f;

#pragma unroll
        for (int ks = 0; ks < 4; ks++) {
            uint32_t ah[4], al[4];
            {
                int row = warp * 16 + (lane & 15);
                int col = ks * 16 + (lane >> 4) * 8;
                uint32_t off = (row * FL_STRIDE + col) * 2;
                ldsm_x4(ah, uQH + off);
                ldsm_x4(al, uQL + off);
            }
#pragma unroll
            for (int j2 = 0; j2 < 4; j2++) {
                int nr = j2 * 16 + (lane & 7) + ((lane & 16) ? 8 : 0);
                int kc = ks * 16 + ((lane & 8) ? 8 : 0);
                uint32_t off = (nr * FL_STRIDE + kc) * 2;
                uint32_t th[4], tl[4];
                ldsm_x4(th, uKH + off);
                ldsm_x4(tl, uKL + off);
                mma_bf16(sc[2 * j2],     ah, &th[0]);
                mma_bf16(sc[2 * j2],     ah, &tl[0]);
                mma_bf16(sc[2 * j2],     al, &th[0]);
                mma_bf16(sc[2 * j2 + 1], ah, &th[2]);
                mma_bf16(sc[2 * j2 + 1], ah, &tl[2]);
                mma_bf16(sc[2 * j2 + 1], al, &th[2]);
            }
        }

        // ---- masks + online softmax on fragments ----
        const int rl0 = warp * 16 + (lane >> 2);   // tile-local row of c[0],c[1]
        const int rl1 = rl0 + 8;                   // tile-local row of c[2],c[3]
#pragma unroll
        for (int j = 0; j < 8; j++) {
            int c = j * 8 + (lane & 3) * 2;
            float2 pd = *(float2*)&pads[c];
            float m00 = 0.f, m01 = 0.f, m10 = 0.f, m11 = 0.f;
            if (diag) {
                float2 a = *(float2*)&Ms[rl0 * 68 + c];
                float2 d = *(float2*)&Ms[rl1 * 68 + c];
                m00 = a.x; m01 = a.y; m10 = d.x; m11 = d.y;
            }
            sc[j][0] = sc[j][0] * 0.125f + pd.x + m00;
            sc[j][1] = sc[j][1] * 0.125f + pd.y + m01;
            sc[j][2] = sc[j][2] * 0.125f + pd.x + m10;
            sc[j][3] = sc[j][3] * 0.125f + pd.y + m11;
        }
        float tm0 = -INFINITY, tm1 = -INFINITY;
#pragma unroll
        for (int j = 0; j < 8; j++) {
            tm0 = fmaxf(tm0, fmaxf(sc[j][0], sc[j][1]));
            tm1 = fmaxf(tm1, fmaxf(sc[j][2], sc[j][3]));
        }
        tm0 = fmaxf(tm0, __shfl_xor_sync(0xffffffffu, tm0, 1));
        tm0 = fmaxf(tm0, __shfl_xor_sync(0xffffffffu, tm0, 2));
        tm1 = fmaxf(tm1, __shfl_xor_sync(0xffffffffu, tm1, 1));
        tm1 = fmaxf(tm1, __shfl_xor_sync(0xffffffffu, tm1, 2));

        const float mn0 = fmaxf(mrow[0], tm0);
        const float mn1 = fmaxf(mrow[1], tm1);
        const float corr0 = __expf(mrow[0] - mn0);
        const float corr1 = __expf(mrow[1] - mn1);
        float rs0 = 0.0f, rs1 = 0.0f;
#pragma unroll
        for (int j = 0; j < 8; j++) {
            sc[j][0] = __expf(sc[j][0] - mn0);
            sc[j][1] = __expf(sc[j][1] - mn0);
            sc[j][2] = __expf(sc[j][2] - mn1);
            sc[j][3] = __expf(sc[j][3] - mn1);
            rs0 += sc[j][0] + sc[j][1];
            rs1 += sc[j][2] + sc[j][3];
        }
        rs0 += __shfl_xor_sync(0xffffffffu, rs0, 1);
        rs0 += __shfl_xor_sync(0xffffffffu, rs0, 2);
        rs1 += __shfl_xor_sync(0xffffffffu, rs1, 1);
        rs1 += __shfl_xor_sync(0xffffffffu, rs1, 2);
        lrow[0] = lrow[0] * corr0 + rs0; mrow[0] = mn0;
        lrow[1] = lrow[1] * corr1 + rs1; mrow[1] = mn1;
#pragma unroll
        for (int j = 0; j < 8; j++) {
            o[j][0] *= corr0; o[j][1] *= corr0;
            o[j][2] *= corr1; o[j][3] *= corr1;
        }

        // ---- store P (hi/lo bf16) to smem [q][k] ----
#pragma unroll
        for (int j = 0; j < 8; j++) {
            int c = j * 8 + (lane & 3) * 2;
            __nv_bfloat162 h0, l0, h1, l1;
            h0.x = __float2bfloat16(sc[j][0]); l0.x = __float2bfloat16(sc[j][0] - __bfloat162float(h0.x));
            h0.y = __float2bfloat16(sc[j][1]); l0.y = __float2bfloat16(sc[j][1] - __bfloat162float(h0.y));
            h1.x = __float2bfloat16(sc[j][2]); l1.x = __float2bfloat16(sc[j][2] - __bfloat162float(h1.x));
            h1.y = __float2bfloat16(sc[j][3]); l1.y = __float2bfloat16(sc[j][3] - __bfloat162float(h1.y));
            *(__nv_bfloat162*)(PH + (rl0 * FL_STRIDE + c) * 2) = h0;
            *(__nv_bfloat162*)(PL + (rl0 * FL_STRIDE + c) * 2) = l0;
            *(__nv_bfloat162*)(PH + (rl1 * FL_STRIDE + c) * 2) = h1;
            *(__nv_bfloat162*)(PL + (rl1 * FL_STRIDE + c) * 2) = l1;
        }
        __syncthreads();

        // ---- O += P @ V (64x64x64, bf16x3; V via ldmatrix.trans) ----
#pragma unroll
        for (int ks = 0; ks < 4; ks++) {
            uint32_t ah[4], al[4];
            {
                int row = warp * 16 + (lane & 15);
                int col = ks * 16 + (lane >> 4) * 8;
                uint32_t off = (row * FL_STRIDE + col) * 2;
                ldsm_x4(ah, uPH + off);
                ldsm_x4(al, uPL + off);
            }
#pragma unroll
            for (int j2 = 0; j2 < 4; j2++) {
                int vr = ks * 16 + (lane & 7) + ((lane & 8) ? 8 : 0);
                int vc = j2 * 16 + ((lane & 16) ? 8 : 0);
                uint32_t off = (vr * FL_STRIDE + vc) * 2;
                uint32_t th[4], tl[4];
                ldsm_x4_t(th, uVH + off);
                ldsm_x4_t(tl, uVL + off);
                mma_bf16(o[2 * j2],     ah, &th[0]);
                mma_bf16(o[2 * j2],     ah, &tl[0]);
                mma_bf16(o[2 * j2],     al, &th[0]);
                mma_bf16(o[2 * j2 + 1], ah, &th[2]);
                mma_bf16(o[2 * j2 + 1], ah, &tl[2]);
                mma_bf16(o[2 * j2 + 1], al, &th[2]);
            }
        }
    }

    // ---- epilogue: normalize, write g_O ----
    const float inv0 = 1.0f / lrow[0];
    const float inv1 = 1.0f / lrow[1];
    const int rg0 = b * S_LEN + q0 + warp * 16 + (lane >> 2);
#pragma unroll
    for (int j = 0; j < 8; j++) {
        int c = h * DK + j * 8 + (lane & 3) * 2;
        float2 w0 = { o[j][0] * inv0, o[j][1] * inv0 };
        float2 w1 = { o[j][2] * inv1, o[j][3] * inv1 };
        *(float2*)&g_O[(size_t)rg0 * DMODEL + c] = w0;
        *(float2*)&g_O[(size_t)(rg0 + 8) * DMODEL + c] = w1;
    }
}

// ---------------------------------------------------------------------------
// Launch
// ---------------------------------------------------------------------------
extern "C" void kernel_launch(void* const* d_in, const int* in_sizes, int n_in,
                              void* d_out, int out_size) {
    const float* query = (const float*)d_in[0];
    const float* key   = (const float*)d_in[1];
    const float* value = (const float*)d_in[2];
    const float* pad   = (const float*)d_in[3];
    const float* look  = (const float*)d_in[4];
    const float* wq    = (const float*)d_in[5];
    const float* wk    = (const float*)d_in[6];
    const float* wv    = (const float*)d_in[7];
    const float* wo    = (const float*)d_in[8];
    const float* bq    = (const float*)d_in[9];
    const float* bk    = (const float*)d_in[10];
    const float* bv    = (const float*)d_in[11];
    const float* bo    = (const float*)d_in[12];
    float* out = (float*)d_out;

    cudaFuncSetAttribute(flash_mma,   cudaFuncAttributeMaxDynamicSharedMemorySize, FL_SMEM);
    cudaFuncSetAttribute(gemm_qkv_tc, cudaFuncAttributeMaxDynamicSharedMemorySize, GEMM_SMEM);
    cudaFuncSetAttribute(gemm_out_tc, cudaFuncAttributeMaxDynamicSharedMemorySize, GEMM_SMEM);

    unsigned short *xhi, *xlo, *yhi, *ylo, *zhi, *zlo, *ohi, *olo;
    cudaGetSymbolAddress((void**)&xhi, g_Xhi);
    cudaGetSymbolAddress((void**)&xlo, g_Xlo);
    cudaGetSymbolAddress((void**)&yhi, g_Yhi);
    cudaGetSymbolAddress((void**)&ylo, g_Ylo);
    cudaGetSymbolAddress((void**)&zhi, g_Zhi);
    cudaGetSymbolAddress((void**)&zlo, g_Zlo);
    cudaGetSymbolAddress((void**)&ohi, g_Ohi);
    cudaGetSymbolAddress((void**)&olo, g_Olo);
    float* o_fp32;
    cudaGetSymbolAddress((void**)&o_fp32, g_O);

    const int n4 = MROWS * DMODEL / 4;

    // 1) split activations to bf16 hi/lo
    split_kernel<<<n4 / 256, 256>>>(query, xhi, xlo, n4);
    split_kernel<<<n4 / 256, 256>>>(key,   yhi, ylo, n4);
    split_kernel<<<n4 / 256, 256>>>(value, zhi, zlo, n4);

    // 2) transpose + split weights
    dim3 gw(DMODEL / 32, DMODEL / 32, 4);
    wsplit_kernel<<<gw, 256>>>(wq, wk, wv, wo);

    // 3) QKV projections (HMMA bf16x3)
    dim3 gq(DMODEL / 128, MROWS / 128, 3);
    gemm_qkv_tc<<<gq, 256, GEMM_SMEM>>>(bq, bk, bv);

    // 4) causal flash attention (HMMA bf16x3)
    dim3 ga(S_LEN / 64, NHEADS, BATCH);
    flash_mma<<<ga, 128, FL_SMEM>>>(pad, look);

    // 5) split O, output projection
    split_kernel<<<n4 / 256, 256>>>(o_fp32, ohi, olo, n4);
    dim3 go(DMODEL / 128, MROWS / 128, 1);
    gemm_out_tc<<<go, 256, GEMM_SMEM>>>(bo, out);
}